// round 1
// baseline (speedup 1.0000x reference)
#include <cuda_runtime.h>

// Spiking1DLIFLayer: B=128, C=512, T=1024
//   mem = mem*beta + x[t] - spk_prev*Vth[c]
//   spk = (mem > Vth[c]) ? 1 : 0
// 65536 independent rows (one per (b,c)), sequential over T.
// HBM-bound: 256MB in + 256MB out. Strategy: smem-staged transpose so all
// global traffic is coalesced float4; recurrence runs from registers.
// __fmul_rn/__fadd_rn keep evaluation order bit-identical to the (non-fused)
// reference to avoid near-threshold spike flips cascading down a row.

#define Bdim 128
#define Cdim 512
#define Tdim 1024
#define NT   64            // threads per block == rows per block
#define TS   64            // time-tile (floats)
#define F4   (TS / 4)      // 16 float4 per row-chunk
#define PITCH (F4 + 1)     // 17 (odd in float4 units -> conflict-free)

__global__ void __launch_bounds__(NT, 8)
lif_kernel(const float* __restrict__ x,
           const float* __restrict__ beta_p,
           const float* __restrict__ vth_p,
           float* __restrict__ out)
{
    __shared__ float4 tile[NT * PITCH];

    const int tid = threadIdx.x;
    const int r0  = blockIdx.x * NT;           // first row of this block
    const float beta = __ldg(beta_p);
    const float vth  = __ldg(vth_p + ((r0 + tid) & (Cdim - 1)));

    const float4* __restrict__ xg = (const float4*)x;
    float4* __restrict__ og = (float4*)out;
    const int row_f4 = Tdim / 4;               // 256 float4 per global row

    float mem = 0.0f;
    float rst = 0.0f;

    for (int t0 = 0; t0 < Tdim; t0 += TS) {
        const int tcol0 = t0 >> 2;             // float4 column base in global row

        // ---- coalesced load: NT*F4 = 1024 float4s, 64 threads ----
        #pragma unroll
        for (int i = 0; i < F4; ++i) {
            int idx = i * NT + tid;
            int row = idx >> 4;                // idx / F4
            int col = idx & 15;                // idx % F4
            tile[row * PITCH + col] = xg[(r0 + row) * row_f4 + tcol0 + col];
        }
        __syncthreads();

        // ---- recurrence: thread owns row `tid`, 64 steps from smem ----
        #pragma unroll
        for (int c = 0; c < F4; ++c) {
            float4 v = tile[tid * PITCH + c];
            float4 s;

            // step macro: exact (mem*beta + x) - rst evaluation order
            #define LIF_STEP(XV, SV)                                   \
                do {                                                   \
                    float t1 = __fmul_rn(mem, beta);                   \
                    float t2 = __fadd_rn(t1, (XV));                    \
                    mem = __fadd_rn(t2, -rst);                         \
                    float spk = (mem > vth) ? 1.0f : 0.0f;             \
                    (SV) = spk;                                        \
                    rst = (mem > vth) ? vth : 0.0f;                    \
                } while (0)

            LIF_STEP(v.x, s.x);
            LIF_STEP(v.y, s.y);
            LIF_STEP(v.z, s.z);
            LIF_STEP(v.w, s.w);
            #undef LIF_STEP

            tile[tid * PITCH + c] = s;         // in-place: same thread, same slot
        }
        __syncthreads();

        // ---- coalesced store ----
        #pragma unroll
        for (int i = 0; i < F4; ++i) {
            int idx = i * NT + tid;
            int row = idx >> 4;
            int col = idx & 15;
            og[(r0 + row) * row_f4 + tcol0 + col] = tile[row * PITCH + col];
        }
        __syncthreads();                       // protect smem before next load
    }
}

extern "C" void kernel_launch(void* const* d_in, const int* in_sizes, int n_in,
                              void* d_out, int out_size)
{
    const float* x    = (const float*)d_in[0];  // (128, 512, 1024) fp32
    const float* beta = (const float*)d_in[1];  // scalar fp32
    const float* vth  = (const float*)d_in[2];  // (512,) fp32
    float* out        = (float*)d_out;          // (128, 512, 1024) fp32

    const int rows = Bdim * Cdim;               // 65536
    lif_kernel<<<rows / NT, NT>>>(x, beta, vth, out);
}

// round 2
// speedup vs baseline: 1.0265x; 1.0265x over previous
#include <cuda_runtime.h>
#include <cstdint>

// Spiking1DLIFLayer: B=128, C=512, T=1024  (row = (b,c), serial recurrence over T)
//   mem = (mem*beta + x[t]) - spk_prev*Vth[c] ;  spk = mem > Vth[c]
// HBM-bound streaming kernel (256MB in + 256MB out, zero reuse).
// R2: cp.async.cg 3-deep pipeline so DRAM reads stay in flight during
// compute/store phases; input bypasses L1. Numerics identical to R1 (rel_err 0).

#define Bdim 128
#define Cdim 512
#define Tdim 1024
#define NT    64                 // threads per block == rows per block
#define TS    32                 // time-tile (floats)
#define F4    (TS / 4)           // 8 float4 per row per tile
#define PITCH (F4 + 1)           // 9 (odd in float4 units -> conflict-free)
#define NBUF  3
#define NTILES (Tdim / TS)       // 32

__device__ __forceinline__ void cp16(uint32_t dst_smem, const float4* src) {
    asm volatile("cp.async.cg.shared.global [%0], [%1], 16;\n"
                 :: "r"(dst_smem), "l"(src));
}
__device__ __forceinline__ void cp_commit() {
    asm volatile("cp.async.commit_group;\n");
}
__device__ __forceinline__ void cp_wait2() {
    asm volatile("cp.async.wait_group 2;\n");
}

__global__ void __launch_bounds__(NT, 8)
lif_kernel(const float* __restrict__ x,
           const float* __restrict__ beta_p,
           const float* __restrict__ vth_p,
           float* __restrict__ out)
{
    __shared__ float4 tile[NBUF][NT * PITCH];

    const int tid = threadIdx.x;
    const int r0  = blockIdx.x * NT;
    const float beta = __ldg(beta_p);
    const float vth  = __ldg(vth_p + ((r0 + tid) & (Cdim - 1)));

    const float4* __restrict__ xg = (const float4*)x;
    float4* __restrict__ og = (float4*)out;
    const int row_f4 = Tdim / 4;                  // 256 float4 per global row

    // ---- prologue: preload tiles 0..2, one commit group each ----
    #pragma unroll
    for (int p = 0; p < NBUF; ++p) {
        const int tcol0 = p * F4;
        uint32_t sbase = (uint32_t)__cvta_generic_to_shared(&tile[p][0]);
        #pragma unroll
        for (int i = 0; i < F4; ++i) {
            int idx = i * NT + tid;
            int row = idx >> 3;                   // idx / F4
            int col = idx & 7;                    // idx % F4
            cp16(sbase + (uint32_t)(row * PITCH + col) * 16u,
                 xg + (size_t)(r0 + row) * row_f4 + tcol0 + col);
        }
        cp_commit();
    }

    float mem = 0.0f;
    float rst = 0.0f;
    int b = 0;

    for (int it = 0; it < NTILES; ++it) {
        cp_wait2();                               // tile `it` landed
        __syncthreads();

        // ---- recurrence: thread owns row `tid`, 32 steps from smem ----
        float4* mybuf = &tile[b][tid * PITCH];
        #pragma unroll
        for (int c = 0; c < F4; ++c) {
            float4 v = mybuf[c];
            float4 s;
            #define LIF_STEP(XV, SV)                                   \
                do {                                                   \
                    float t1 = __fmul_rn(mem, beta);                   \
                    float t2 = __fadd_rn(t1, (XV));                    \
                    mem = __fadd_rn(t2, -rst);                         \
                    float spk = (mem > vth) ? 1.0f : 0.0f;             \
                    (SV) = spk;                                        \
                    rst = (mem > vth) ? vth : 0.0f;                    \
                } while (0)
            LIF_STEP(v.x, s.x);
            LIF_STEP(v.y, s.y);
            LIF_STEP(v.z, s.z);
            LIF_STEP(v.w, s.w);
            #undef LIF_STEP
            mybuf[c] = s;                         // in-place spike staging
        }
        __syncthreads();

        // ---- coalesced store of tile `it` ----
        {
            const int tcol0 = it * F4;
            #pragma unroll
            for (int i = 0; i < F4; ++i) {
                int idx = i * NT + tid;
                int row = idx >> 3;
                int col = idx & 7;
                og[(size_t)(r0 + row) * row_f4 + tcol0 + col] =
                    tile[b][row * PITCH + col];
            }
        }
        __syncthreads();                          // buf reads done before refill

        // ---- refill buf b with tile it+3 (if any); always commit a group ----
        const int ip = it + NBUF;
        if (ip < NTILES) {
            const int tcol0 = ip * F4;
            uint32_t sbase = (uint32_t)__cvta_generic_to_shared(&tile[b][0]);
            #pragma unroll
            for (int i = 0; i < F4; ++i) {
                int idx = i * NT + tid;
                int row = idx >> 3;
                int col = idx & 7;
                cp16(sbase + (uint32_t)(row * PITCH + col) * 16u,
                     xg + (size_t)(r0 + row) * row_f4 + tcol0 + col);
            }
        }
        cp_commit();

        b = (b == NBUF - 1) ? 0 : b + 1;
    }
}

extern "C" void kernel_launch(void* const* d_in, const int* in_sizes, int n_in,
                              void* d_out, int out_size)
{
    const float* x    = (const float*)d_in[0];  // (128, 512, 1024) fp32
    const float* beta = (const float*)d_in[1];  // scalar fp32
    const float* vth  = (const float*)d_in[2];  // (512,) fp32
    float* out        = (float*)d_out;          // (128, 512, 1024) fp32

    lif_kernel<<<(Bdim * Cdim) / NT, NT>>>(x, beta, vth, out);
}